// round 10
// baseline (speedup 1.0000x reference)
#include <cuda_runtime.h>

#define Bsz 4096
#define Tsz 256
#define Fsz 64
#define Hsz 16
#define Dsz 64
#define BB  32      // rows per block
#define NT  256     // 8 warps; warp owns 4 rows end-to-end

// ---------- packed f32x2 helpers ----------
__device__ __forceinline__ unsigned long long ffma2_(unsigned long long a,
                                                     unsigned long long b,
                                                     unsigned long long c) {
    unsigned long long d;
    asm("fma.rn.f32x2 %0, %1, %2, %3;" : "=l"(d) : "l"(a), "l"(b), "l"(c));
    return d;
}
__device__ __forceinline__ unsigned long long pack2_(float lo, float hi) {
    unsigned long long d;
    asm("mov.b64 %0, {%1, %2};" : "=l"(d) : "f"(lo), "f"(hi));
    return d;
}
__device__ __forceinline__ float2 unpack2_(unsigned long long v) {
    float2 r;
    asm("mov.b64 {%0, %1}, %2;" : "=f"(r.x), "=f"(r.y) : "l"(v));
    return r;
}
__device__ __forceinline__ float sigmoidf_(float v) {
    return __fdividef(1.0f, 1.0f + __expf(-v));
}

__global__ __launch_bounds__(NT, 1)
void lstm_regW_kernel(const float* __restrict__ x,
                      const float* __restrict__ W,
                      const float* __restrict__ U,
                      const float* __restrict__ b,
                      const float* __restrict__ Wd,
                      const float* __restrict__ bd,
                      float* __restrict__ out)
{
    __shared__ float xs[BB][68];   // x tile; stride 272B (16B mult)
    __shared__ float zs[BB][80];   // z exchange; stride 320B -> conflict-free gate reads
    __shared__ float hs[BB][16];   // h state [row][unit]

    const int tid  = threadIdx.x;
    const int warp = tid >> 5;
    const int lane = tid & 31;
    const int wr0  = warp * 4;              // warp's first row (block-local)

    // compute mapping: lane owns cols c0 = 2*lane, c0+1 (covers 64 cols)
    const int c0 = 2 * lane;
    // x staging mapping: row wr0+ro, floats [8*f8, 8*f8+8)
    const int ro = lane >> 3;
    const int f8 = lane & 7;
    // gate/dense mapping: rows wr0+gr and wr0+gr+2, unit gu
    const int gr = lane >> 4;
    const int gu = lane & 15;

    // init h state (warp-private rows)
    hs[wr0 + gr][gu]     = 0.0f;
    hs[wr0 + gr + 2][gu] = 0.0f;

    // ---- W (full k=64, this lane's 2 cols) into registers as k-pairs ----
    unsigned long long Wr[32][2];
    #pragma unroll
    for (int kp = 0; kp < 32; kp++) {
        #pragma unroll
        for (int j = 0; j < 2; j++)
            Wr[kp][j] = pack2_(W[(2 * kp) * 64 + c0 + j],
                               W[(2 * kp + 1) * 64 + c0 + j]);
    }
    // ---- U k-pairs ----
    unsigned long long Ur[8][2];
    #pragma unroll
    for (int kp = 0; kp < 8; kp++) {
        #pragma unroll
        for (int j = 0; j < 2; j++)
            Ur[kp][j] = pack2_(U[(2 * kp) * 64 + c0 + j],
                               U[(2 * kp + 1) * 64 + c0 + j]);
    }
    const unsigned long long bini0 = pack2_(b[c0],     0.0f);
    const unsigned long long bini1 = pack2_(b[c0 + 1], 0.0f);

    // x prefetch pointers (row wr0+ro of this block)
    const size_t growx = (size_t)blockIdx.x * BB + wr0 + ro;
    const float* xsrc = x + growx * Tsz * Fsz + 8 * f8;
    float4 xnA = *(const float4*)(xsrc);
    float4 xnB = *(const float4*)(xsrc + 4);

    float ca = 0.0f, cb = 0.0f;   // cell state for rows (wr0+gr) and (wr0+gr+2)
    __syncwarp();

    for (int t = 0; t < Tsz; t++) {
        // stage x tile (warp-private rows)
        *(float4*)&xs[wr0 + ro][8 * f8]     = xnA;
        *(float4*)&xs[wr0 + ro][8 * f8 + 4] = xnB;
        __syncwarp();
        if (t + 1 < Tsz) {
            xnA = *(const float4*)(xsrc + (size_t)(t + 1) * Fsz);
            xnB = *(const float4*)(xsrc + (size_t)(t + 1) * Fsz + 4);
        }

        // ---- z[4 rows][2 cols] = b + x@W + h@U  (acc packed over k) ----
        unsigned long long acc[4][2];
        #pragma unroll
        for (int i = 0; i < 4; i++) { acc[i][0] = bini0; acc[i][1] = bini1; }

        #pragma unroll
        for (int i = 0; i < 4; i++) {
            const float* xrow = &xs[wr0 + i][0];
            #pragma unroll
            for (int l4 = 0; l4 < 16; l4++) {
                const ulonglong2 xa = *(const ulonglong2*)(xrow + 4 * l4);
                acc[i][0] = ffma2_(xa.x, Wr[2 * l4][0],     acc[i][0]);
                acc[i][1] = ffma2_(xa.x, Wr[2 * l4][1],     acc[i][1]);
                acc[i][0] = ffma2_(xa.y, Wr[2 * l4 + 1][0], acc[i][0]);
                acc[i][1] = ffma2_(xa.y, Wr[2 * l4 + 1][1], acc[i][1]);
            }
            const float* hrow = &hs[wr0 + i][0];
            #pragma unroll
            for (int l4 = 0; l4 < 4; l4++) {
                const ulonglong2 ha = *(const ulonglong2*)(hrow + 4 * l4);
                acc[i][0] = ffma2_(ha.x, Ur[2 * l4][0],     acc[i][0]);
                acc[i][1] = ffma2_(ha.x, Ur[2 * l4][1],     acc[i][1]);
                acc[i][0] = ffma2_(ha.y, Ur[2 * l4 + 1][0], acc[i][0]);
                acc[i][1] = ffma2_(ha.y, Ur[2 * l4 + 1][1], acc[i][1]);
            }
            const float2 v0 = unpack2_(acc[i][0]);
            const float2 v1 = unpack2_(acc[i][1]);
            *(float2*)&zs[wr0 + i][c0] = make_float2(v0.x + v0.y, v1.x + v1.y);
        }
        __syncwarp();

        // ---- gates: rows wr0+gr and wr0+gr+2, unit gu ----
        {
            int r = wr0 + gr;
            float ig = sigmoidf_(zs[r][gu]);
            float fg = sigmoidf_(zs[r][gu + 16]);
            float gg = fmaxf(zs[r][gu + 32], 0.0f);
            float og = sigmoidf_(zs[r][gu + 48]);
            ca = fg * ca + ig * gg;
            hs[r][gu] = og * fmaxf(ca, 0.0f);

            r = wr0 + gr + 2;
            ig = sigmoidf_(zs[r][gu]);
            fg = sigmoidf_(zs[r][gu + 16]);
            gg = fmaxf(zs[r][gu + 32], 0.0f);
            og = sigmoidf_(zs[r][gu + 48]);
            cb = fg * cb + ig * gg;
            hs[r][gu] = og * fmaxf(cb, 0.0f);
        }
        __syncwarp();
    }

    // ---- dense(D=64, sigmoid) + sum-normalize ----
    // lane handles rows {wr0+gr, wr0+gr+2}, cols 4*gu..4*gu+3
    float d[2][4];
    {
        const float4 bdv = *(const float4*)&bd[4 * gu];
        d[0][0] = d[1][0] = bdv.x; d[0][1] = d[1][1] = bdv.y;
        d[0][2] = d[1][2] = bdv.z; d[0][3] = d[1][3] = bdv.w;
    }
    const int r0 = wr0 + gr, r1 = wr0 + gr + 2;
    #pragma unroll
    for (int k = 0; k < 16; k++) {
        const float4 wv = *(const float4*)&Wd[k * 64 + 4 * gu];
        const float h0 = hs[r0][k];
        const float h1 = hs[r1][k];
        d[0][0] += h0 * wv.x; d[0][1] += h0 * wv.y; d[0][2] += h0 * wv.z; d[0][3] += h0 * wv.w;
        d[1][0] += h1 * wv.x; d[1][1] += h1 * wv.y; d[1][2] += h1 * wv.z; d[1][3] += h1 * wv.w;
    }
    const int rows[2] = {r0, r1};
    #pragma unroll
    for (int rr = 0; rr < 2; rr++) {
        #pragma unroll
        for (int j = 0; j < 4; j++) d[rr][j] = sigmoidf_(d[rr][j]);
        float s = d[rr][0] + d[rr][1] + d[rr][2] + d[rr][3];
        #pragma unroll
        for (int off = 1; off < 16; off <<= 1)   // reduce over the 16 gu-lanes
            s += __shfl_xor_sync(0xffffffffu, s, off);
        const float inv = __fdividef(1.0f, s);
        const size_t grow = (size_t)blockIdx.x * BB + rows[rr];
        *(float4*)&out[grow * Dsz + 4 * gu] =
            make_float4(d[rr][0] * inv, d[rr][1] * inv, d[rr][2] * inv, d[rr][3] * inv);
    }
}

extern "C" void kernel_launch(void* const* d_in, const int* in_sizes, int n_in,
                              void* d_out, int out_size) {
    const float* x  = (const float*)d_in[0];
    const float* W  = (const float*)d_in[1];
    const float* U  = (const float*)d_in[2];
    const float* b  = (const float*)d_in[3];
    const float* Wd = (const float*)d_in[4];
    const float* bd = (const float*)d_in[5];
    float* out = (float*)d_out;
    lstm_regW_kernel<<<Bsz / BB, NT>>>(x, W, U, b, Wd, bd, out);
}

// round 12
// speedup vs baseline: 1.4003x; 1.4003x over previous
#include <cuda_runtime.h>

#define Bsz 4096
#define Tsz 256
#define Fsz 64
#define Hsz 16
#define Dsz 64
#define BB  32     // rows per block
#define NT  256    // 8 warps; warp owns 4 rows end-to-end
#define TC  16     // timesteps per chunk
#define SC  4      // timesteps per subchunk (x staging granularity)

#define ZT  (BB * 68)      // zbuf t-stride in floats (32*68 = 2176)
#define ZR  68              // zbuf row stride
#define XR  (SC * 68)       // xsub row stride (272)
#define XT  68              // xsub t stride
#define SMEM_BYTES ((TC * BB * ZR + BB * SC * XT + BB * 16) * 4)  // 176128

// ---------- packed f32x2 helpers ----------
__device__ __forceinline__ unsigned long long ffma2_(unsigned long long a,
                                                     unsigned long long b,
                                                     unsigned long long c) {
    unsigned long long d;
    asm("fma.rn.f32x2 %0, %1, %2, %3;" : "=l"(d) : "l"(a), "l"(b), "l"(c));
    return d;
}
__device__ __forceinline__ unsigned long long pack2_(float lo, float hi) {
    unsigned long long d;
    asm("mov.b64 %0, {%1, %2};" : "=l"(d) : "f"(lo), "f"(hi));
    return d;
}
__device__ __forceinline__ float2 unpack2_(unsigned long long v) {
    float2 r;
    asm("mov.b64 {%0, %1}, %2;" : "=f"(r.x), "=f"(r.y) : "l"(v));
    return r;
}
__device__ __forceinline__ float sigmoidf_(float v) {
    return __fdividef(1.0f, 1.0f + __expf(-v));
}

__global__ __launch_bounds__(NT, 1)
void lstm_chunk_kernel(const float* __restrict__ x,
                       const float* __restrict__ W,
                       const float* __restrict__ U,
                       const float* __restrict__ b,
                       const float* __restrict__ Wd,
                       const float* __restrict__ bd,
                       float* __restrict__ out)
{
    extern __shared__ float sm[];
    float* zbuf = sm;                       // [TC][BB][ZR]
    float* xsub = sm + TC * BB * ZR;        // [BB][SC][XT]
    float* hs   = xsub + BB * SC * XT;      // [BB][16]

    const int tid  = threadIdx.x;
    const int warp = tid >> 5;
    const int lane = tid & 31;
    const int wr0  = warp * 4;              // warp's 4 rows: wr0..wr0+3
    const int c0   = 2 * lane;              // lane's 2 z-columns
    const int gr   = lane >> 4;             // gate rows: wr0+gr, wr0+gr+2
    const int gu   = lane & 15;             // gate unit

    // W full k=64, lane's 2 cols, as k-pairs: 128 regs
    unsigned long long Wr[32][2];
    #pragma unroll
    for (int kp = 0; kp < 32; kp++) {
        #pragma unroll
        for (int j = 0; j < 2; j++)
            Wr[kp][j] = pack2_(W[(2 * kp) * 64 + c0 + j],
                               W[(2 * kp + 1) * 64 + c0 + j]);
    }
    // U k-pairs: 32 regs
    unsigned long long Ur[8][2];
    #pragma unroll
    for (int kp = 0; kp < 8; kp++) {
        #pragma unroll
        for (int j = 0; j < 2; j++)
            Ur[kp][j] = pack2_(U[(2 * kp) * 64 + c0 + j],
                               U[(2 * kp + 1) * 64 + c0 + j]);
    }
    const unsigned long long bi0 = pack2_(b[c0],     0.0f);
    const unsigned long long bi1 = pack2_(b[c0 + 1], 0.0f);

    // init h state (warp-private rows)
    hs[(wr0 + gr) * 16 + gu]     = 0.0f;
    hs[(wr0 + gr + 2) * 16 + gu] = 0.0f;
    __syncwarp();

    float ca = 0.0f, cb = 0.0f;
    const size_t growbase = (size_t)blockIdx.x * BB;

    for (int ch = 0; ch < Tsz / TC; ch++) {
        // ================= Phase A: z0 = b + x@W for TC timesteps =================
        for (int sub = 0; sub < TC / SC; sub++) {
            const int t0 = ch * TC + sub * SC;
            // warp loads its own rows' x subtile (4 rows x 4 t x 64 f)
            #pragma unroll
            for (int it = 0; it < 8; it++) {
                const int f  = lane + 32 * it;       // 0..255 float4 index
                const int f4 = f & 15;
                const int tt = (f >> 4) & 3;
                const int r  = f >> 6;               // 0..3
                const float4 v = *(const float4*)&x[((growbase + wr0 + r) * Tsz
                                                     + (t0 + tt)) * Fsz + 4 * f4];
                *(float4*)&xsub[(wr0 + r) * XR + tt * XT + 4 * f4] = v;
            }
            __syncwarp();
            // 16 (row,t) items, 2 in flight (8 independent FFMA2 chains)
            #pragma unroll
            for (int i = 0; i < 16; i += 2) {
                const int r  = wr0 + (i & 3);        // i even -> (i&3) in {0,2}
                const int tt = i >> 2;
                const float* xr0 = &xsub[r * XR + tt * XT];
                const float* xr1 = xr0 + XR;         // row r+1, same tt
                unsigned long long a00 = bi0, a01 = bi1, a10 = bi0, a11 = bi1;
                #pragma unroll
                for (int kk = 0; kk < 16; kk++) {
                    const ulonglong2 p0 = *(const ulonglong2*)(xr0 + 4 * kk);
                    const ulonglong2 p1 = *(const ulonglong2*)(xr1 + 4 * kk);
                    a00 = ffma2_(p0.x, Wr[2 * kk][0],     a00);
                    a01 = ffma2_(p0.x, Wr[2 * kk][1],     a01);
                    a10 = ffma2_(p1.x, Wr[2 * kk][0],     a10);
                    a11 = ffma2_(p1.x, Wr[2 * kk][1],     a11);
                    a00 = ffma2_(p0.y, Wr[2 * kk + 1][0], a00);
                    a01 = ffma2_(p0.y, Wr[2 * kk + 1][1], a01);
                    a10 = ffma2_(p1.y, Wr[2 * kk + 1][0], a10);
                    a11 = ffma2_(p1.y, Wr[2 * kk + 1][1], a11);
                }
                const int zt = sub * SC + tt;
                const float2 u0 = unpack2_(a00), u1 = unpack2_(a01);
                *(float2*)&zbuf[zt * ZT + r * ZR + c0] =
                    make_float2(u0.x + u0.y, u1.x + u1.y);
                const float2 v0 = unpack2_(a10), v1 = unpack2_(a11);
                *(float2*)&zbuf[zt * ZT + (r + 1) * ZR + c0] =
                    make_float2(v0.x + v0.y, v1.x + v1.y);
            }
            __syncwarp();   // xsub reuse guard
        }

        // ================= Phase B: TC recurrence steps (h@U only) =================
        for (int t = 0; t < TC; t++) {
            float* zrow = &zbuf[t * ZT];
            #pragma unroll
            for (int r = 0; r < 4; r++) {
                const float* hrow = &hs[(wr0 + r) * 16];
                unsigned long long a0 = 0ULL, a1 = 0ULL;
                #pragma unroll
                for (int j = 0; j < 4; j++) {
                    const ulonglong2 hp = *(const ulonglong2*)(hrow + 4 * j);
                    a0 = ffma2_(hp.x, Ur[2 * j][0],     a0);
                    a1 = ffma2_(hp.x, Ur[2 * j][1],     a1);
                    a0 = ffma2_(hp.y, Ur[2 * j + 1][0], a0);
                    a1 = ffma2_(hp.y, Ur[2 * j + 1][1], a1);
                }
                const float2 h0 = unpack2_(a0), h1 = unpack2_(a1);
                float2 zf = *(float2*)&zrow[(wr0 + r) * ZR + c0];
                zf.x += h0.x + h0.y;
                zf.y += h1.x + h1.y;
                *(float2*)&zrow[(wr0 + r) * ZR + c0] = zf;
            }
            __syncwarp();
            // gates: rows wr0+gr and wr0+gr+2, unit gu
            {
                int r = wr0 + gr;
                const float* zr = &zrow[r * ZR];
                float ig = sigmoidf_(zr[gu]);
                float fg = sigmoidf_(zr[gu + 16]);
                float gg = fmaxf(zr[gu + 32], 0.0f);
                float og = sigmoidf_(zr[gu + 48]);
                ca = fg * ca + ig * gg;
                hs[r * 16 + gu] = og * fmaxf(ca, 0.0f);

                r = wr0 + gr + 2;
                const float* zr2 = &zrow[r * ZR];
                ig = sigmoidf_(zr2[gu]);
                fg = sigmoidf_(zr2[gu + 16]);
                gg = fmaxf(zr2[gu + 32], 0.0f);
                og = sigmoidf_(zr2[gu + 48]);
                cb = fg * cb + ig * gg;
                hs[r * 16 + gu] = og * fmaxf(cb, 0.0f);
            }
            __syncwarp();
        }
    }

    // ================= dense(D=64, sigmoid) + sum-normalize =================
    float d[2][4];
    {
        const float4 bdv = *(const float4*)&bd[4 * gu];
        d[0][0] = d[1][0] = bdv.x; d[0][1] = d[1][1] = bdv.y;
        d[0][2] = d[1][2] = bdv.z; d[0][3] = d[1][3] = bdv.w;
    }
    const int r0 = wr0 + gr, r1 = wr0 + gr + 2;
    #pragma unroll
    for (int k = 0; k < 16; k++) {
        const float4 wv = *(const float4*)&Wd[k * 64 + 4 * gu];
        const float h0 = hs[r0 * 16 + k];
        const float h1 = hs[r1 * 16 + k];
        d[0][0] += h0 * wv.x; d[0][1] += h0 * wv.y; d[0][2] += h0 * wv.z; d[0][3] += h0 * wv.w;
        d[1][0] += h1 * wv.x; d[1][1] += h1 * wv.y; d[1][2] += h1 * wv.z; d[1][3] += h1 * wv.w;
    }
    const int rows[2] = {r0, r1};
    #pragma unroll
    for (int rr = 0; rr < 2; rr++) {
        #pragma unroll
        for (int j = 0; j < 4; j++) d[rr][j] = sigmoidf_(d[rr][j]);
        float s = d[rr][0] + d[rr][1] + d[rr][2] + d[rr][3];
        #pragma unroll
        for (int off = 1; off < 16; off <<= 1)     // reduce over the 16 gu-lanes
            s += __shfl_xor_sync(0xffffffffu, s, off);
        const float inv = __fdividef(1.0f, s);
        const size_t grow = growbase + rows[rr];
        *(float4*)&out[grow * Dsz + 4 * gu] =
            make_float4(d[rr][0] * inv, d[rr][1] * inv, d[rr][2] * inv, d[rr][3] * inv);
    }
}

extern "C" void kernel_launch(void* const* d_in, const int* in_sizes, int n_in,
                              void* d_out, int out_size) {
    const float* x  = (const float*)d_in[0];
    const float* W  = (const float*)d_in[1];
    const float* U  = (const float*)d_in[2];
    const float* b  = (const float*)d_in[3];
    const float* Wd = (const float*)d_in[4];
    const float* bd = (const float*)d_in[5];
    float* out = (float*)d_out;

    cudaFuncSetAttribute(lstm_chunk_kernel,
                         cudaFuncAttributeMaxDynamicSharedMemorySize, SMEM_BYTES);
    lstm_chunk_kernel<<<Bsz / BB, NT, SMEM_BYTES>>>(x, W, U, b, Wd, bd, out);
}